// round 13
// baseline (speedup 1.0000x reference)
#include <cuda_runtime.h>
#include <math.h>
#include <stdint.h>

#define BATCH 64
#define NPTS  512
#define DIM   512
#define NIDS  32                        // track ids are in [-1, 32)
#define IDS_PER_BLK 2
#define GRID  (BATCH * (NIDS / IDS_PER_BLK))   // 1024 blocks
#define DTHREADS 128
#define DWARPS 4                        // warp w: id (w>>1), half (w&1)
#define F4 (DIM / 4)                    // 128 float4 per row

__device__ __constant__ float c_margin = 0.3f;
__device__ __constant__ float c_eps    = 1e-6f;

// scratch (no allocations allowed) — zero-initialized; last block resets.
__device__ float        g_tot;
__device__ int          g_cntall;
__device__ unsigned int g_ticket;

// identity form: a' = a+eps; acc += a'*(a'-2Q)  [ + |Q|^2 added later ]
#define ACCC(av, Pv, Nv, sap, san)               \
    do {                                         \
        const float a_ = (av) + eps;             \
        float t_ = fmaf(-2.0f, (Pv), a_);        \
        sap = fmaf(a_, t_, sap);                 \
        t_ = fmaf(-2.0f, (Nv), a_);              \
        san = fmaf(a_, t_, san);                 \
    } while (0)
#define ACCK(a4, P4, N4, sap, san)                    \
    do {                                              \
        ACCC((a4).x, (P4).x, (N4).x, sap, san);       \
        ACCC((a4).y, (P4).y, (N4).y, sap, san);       \
        ACCC((a4).z, (P4).z, (N4).z, sap, san);       \
        ACCC((a4).w, (P4).w, (N4).w, sap, san);       \
    } while (0)
#define ACCP1(av, Pv, sap)                            \
    do {                                              \
        const float a_ = (av) + eps;                  \
        const float t_ = fmaf(-2.0f, (Pv), a_);       \
        sap = fmaf(a_, t_, sap);                      \
    } while (0)
#define ACCPK(a4, P4, sap)                            \
    do {                                              \
        ACCP1((a4).x, (P4).x, sap);                   \
        ACCP1((a4).y, (P4).y, sap);                   \
        ACCP1((a4).z, (P4).z, sap);                   \
        ACCP1((a4).w, (P4).w, sap);                   \
    } while (0)
#define NRM4(v, acc)                                  \
    do {                                              \
        acc = fmaf((v).x, (v).x, acc);                \
        acc = fmaf((v).y, (v).y, acc);                \
        acc = fmaf((v).z, (v).z, acc);                \
        acc = fmaf((v).w, (v).w, acc);                \
    } while (0)

// ---------------------------------------------------------------------------
// R13: R12's register-resident P/N rows + identity-form distance (minimal
// 64MB traffic, proven), but fixed parallelism: 2 ids/block -> 1024 blocks,
// 2 warps share an id (alternate anchors), no smem staging (plain LDG, 8
// independent LDG.128 per 2-anchor iteration). R12's grid of 512 capped the
// chip at 14 warps/SM; this targets ~2x that with identical inner math.
// ---------------------------------------------------------------------------
__global__ void __launch_bounds__(DTHREADS)
dist_kernel(const float* __restrict__ feats,
            const int*   __restrict__ ids,
            float*       __restrict__ out,
            int out_size)
{
    const int blk    = blockIdx.x;
    const int b      = blk >> 4;                 // batch
    const int idbase = (blk & 15) * IDS_PER_BLK;
    const int t      = threadIdx.x;
    const int wid    = t >> 5;
    const int lane   = t & 31;

    __shared__ int s_list[NPTS];                 // grouped by id (block-local)
    __shared__ int s_first[NIDS];
    __shared__ int s_second[NIDS];
    __shared__ int s_count[NIDS];
    __shared__ int s_sub[IDS_PER_BLK];
    __shared__ int s_j1, s_j2, s_idj1, s_nvalid;
    __shared__ float s_tot;
    __shared__ int   s_cnt;

    if (t < NIDS) {
        s_first[t]  = 0x7fffffff;
        s_second[t] = 0x7fffffff;
        s_count[t]  = 0;
    }
    if (t < IDS_PER_BLK) s_sub[t] = 0;
    if (t == 0) {
        s_j1 = 0x7fffffff; s_j2 = 0x7fffffff;
        s_nvalid = 0; s_tot = 0.0f; s_cnt = 0;
    }
    __syncthreads();

    const int* __restrict__ bid = ids + b * NPTS;

    // Pass 1: 4 ids per thread (int4); first per id, counts, first valid.
    const int4 iv = ((const int4*)bid)[t];
    const int idr[4] = { iv.x, iv.y, iv.z, iv.w };
    int lv = 0;
    #pragma unroll
    for (int r = 0; r < 4; ++r) {
        const int i = 4 * t + r;
        if (idr[r] >= 0) {
            lv++;
            atomicMin(&s_j1, i);
            atomicMin(&s_first[idr[r]], i);
            atomicAdd(&s_count[idr[r]], 1);
        }
    }
    #pragma unroll
    for (int o = 16; o > 0; o >>= 1) lv += __shfl_xor_sync(0xFFFFFFFFu, lv, o);
    if (lane == 0) atomicAdd(&s_nvalid, lv);
    __syncthreads();
    if (t == 0) s_idj1 = (s_j1 < NPTS) ? bid[s_j1] : -2;
    __syncthreads();

    // Pass 2: second per id, j2, grouped anchor-list append for my 2 ids.
    const int idj1   = s_idj1;
    const int nvalid = s_nvalid;
    #pragma unroll
    for (int r = 0; r < 4; ++r) {
        const int i  = 4 * t + r;
        const int id = idr[r];
        if (id >= 0) {
            if (i != s_first[id]) atomicMin(&s_second[id], i);
            if (id != idj1)       atomicMin(&s_j2, i);
            if (id >= idbase && id < idbase + IDS_PER_BLK) {
                const int cmv = s_count[id];
                if (cmv >= 2 && nvalid > cmv) {          // ok(id)
                    const int c   = id - idbase;
                    const int off = (c == 0) ? 0 : s_count[idbase];
                    const int k   = atomicAdd(&s_sub[c], 1);
                    s_list[off + k] = i;
                }
            }
        }
    }
    __syncthreads();

    float w_tot = 0.0f;
    int   w_cnt = 0;

    const float4* __restrict__ base4 =
        (const float4*)(feats + (size_t)b * NPTS * DIM);
    const float eps = c_eps;

    const int c  = wid >> 1;            // which of my 2 ids
    const int h  = wid & 1;             // which half of its anchors
    const int m  = idbase + c;
    const int cm = s_count[m];
    const bool ok = (cm >= 2) && (nvalid > cm);

    if (ok) {
        const int first  = s_first[m];
        const int second = s_second[m];
        const int nidx   = (idj1 != m) ? s_j1 : s_j2;
        const int off    = (c == 0) ? 0 : s_count[idbase];

        // Pos/neg rows -> registers; norms -> warp-uniform scalars.
        const float4* __restrict__ fP = base4 + (size_t)first * F4;
        const float4* __restrict__ fN = base4 + (size_t)nidx  * F4;
        const float4 P0 = fP[lane], P1 = fP[lane+32], P2 = fP[lane+64], P3 = fP[lane+96];
        const float4 N0 = fN[lane], N1 = fN[lane+32], N2 = fN[lane+64], N3 = fN[lane+96];
        float np = 0.0f, nn = 0.0f;
        NRM4(P0, np); NRM4(P1, np); NRM4(P2, np); NRM4(P3, np);
        NRM4(N0, nn); NRM4(N1, nn); NRM4(N2, nn); NRM4(N3, nn);
        #pragma unroll
        for (int o = 16; o > 0; o >>= 1) {
            np += __shfl_xor_sync(0xFFFFFFFFu, np, o);
            nn += __shfl_xor_sync(0xFFFFFFFFu, nn, o);
        }

        // This warp's anchors: list slots h, h+2, h+4, ... ; 2 per iteration.
        for (int s = h; s < cm; s += 4) {
            const int iA  = s_list[off + s];
            const bool vB = (s + 2) < cm;
            const int iB  = vB ? s_list[off + s + 2] : iA;

            const float4* __restrict__ fA = base4 + (size_t)iA * F4;
            const float4* __restrict__ fB = base4 + (size_t)iB * F4;
            const float4 A0 = fA[lane], A1 = fA[lane+32],
                         A2 = fA[lane+64], A3 = fA[lane+96];
            const float4 B0 = fB[lane], B1 = fB[lane+32],
                         B2 = fB[lane+64], B3 = fB[lane+96];

            float sapA = 0.0f, sanA = 0.0f, sapB = 0.0f, sanB = 0.0f;
            ACCK(A0, P0, N0, sapA, sanA);  ACCK(B0, P0, N0, sapB, sanB);
            ACCK(A1, P1, N1, sapA, sanA);  ACCK(B1, P1, N1, sapB, sanB);
            ACCK(A2, P2, N2, sapA, sanA);  ACCK(B2, P2, N2, sapB, sanB);
            ACCK(A3, P3, N3, sapA, sanA);  ACCK(B3, P3, N3, sapB, sanB);

            float napA = np, napB = np;
            if (iA == first || (vB && iB == first)) {
                // rare warp-uniform path: that anchor pairs with `second`
                const float4* __restrict__ fS = base4 + (size_t)second * F4;
                const float4 S0 = fS[lane],    S1 = fS[lane+32];
                const float4 S2 = fS[lane+64], S3 = fS[lane+96];
                float ns = 0.0f;
                NRM4(S0, ns); NRM4(S1, ns); NRM4(S2, ns); NRM4(S3, ns);
                #pragma unroll
                for (int o = 16; o > 0; o >>= 1)
                    ns += __shfl_xor_sync(0xFFFFFFFFu, ns, o);
                float sp = 0.0f;
                if (iA == first) {
                    ACCPK(A0, S0, sp); ACCPK(A1, S1, sp);
                    ACCPK(A2, S2, sp); ACCPK(A3, S3, sp);
                    sapA = sp; napA = ns;
                } else {
                    ACCPK(B0, S0, sp); ACCPK(B1, S1, sp);
                    ACCPK(B2, S2, sp); ACCPK(B3, S3, sp);
                    sapB = sp; napB = ns;
                }
            }

            #pragma unroll
            for (int o = 16; o > 0; o >>= 1) {
                sapA += __shfl_xor_sync(0xFFFFFFFFu, sapA, o);
                sanA += __shfl_xor_sync(0xFFFFFFFFu, sanA, o);
                sapB += __shfl_xor_sync(0xFFFFFFFFu, sapB, o);
                sanB += __shfl_xor_sync(0xFFFFFFFFu, sanB, o);
            }
            if (lane == 0) {
                float per = sqrtf(sapA + napA) - sqrtf(sanA + nn) + c_margin;
                if (per > 0.0f) w_tot += per;
                w_cnt++;
                if (vB) {
                    per = sqrtf(sapB + napB) - sqrtf(sanB + nn) + c_margin;
                    if (per > 0.0f) w_tot += per;
                    w_cnt++;
                }
            }
        }
    }

    if (lane == 0) {
        atomicAdd(&s_tot, w_tot);
        atomicAdd(&s_cnt, w_cnt);
    }
    __syncthreads();

    if (t == 0) {
        atomicAdd(&g_tot, s_tot);
        atomicAdd(&g_cntall, s_cnt);
        __threadfence();
        const unsigned int old = atomicAdd(&g_ticket, 1u);
        if (old == GRID - 1) {
            __threadfence();                 // see all blocks' adds
            const float T = g_tot;
            const int   C = g_cntall;
            const float loss = (C > 0) ? (T / (float)C) : 0.0f;
            if (out_size > 0) out[0] = loss; // tracking_loss
            if (out_size > 1) out[1] = loss; // loss_triplet
            if (out_size > 2) out[2] = 0.0f; // loss_id
            g_tot    = 0.0f;                 // reset for next graph replay
            g_cntall = 0;
            g_ticket = 0;
            __threadfence();
        }
    }
}

extern "C" void kernel_launch(void* const* d_in, const int* in_sizes, int n_in,
                              void* d_out, int out_size)
{
    const float* feats = (const float*)d_in[0];
    const int*   ids   = (const int*)d_in[1];
    float*       out   = (float*)d_out;

    dist_kernel<<<GRID, DTHREADS>>>(feats, ids, out, out_size);
}